// round 1
// baseline (speedup 1.0000x reference)
#include <cuda_runtime.h>
#include <cuda_bf16.h>

// out[b] = -sum_ti Et[b][ti] * ( sum_zi Ez[b][zi] * (W[zi][ti]+eps) )
// Ez[b][zi] = exp(-50*(z[b]-zm[zi])^2), Et[b][ti] = exp(-50*(t[b]-tm[ti])^2)

#define BB 128      // batch rows per CTA
#define NZ 128
#define NT 128
#define THREADS 256

// smem layout (bytes)
#define WDUP_BYTES (NZ * NT * 8)        // 131072 : float2-duplicated weights, [zi][ti]
#define EZ_BYTES   (NZ * BB * 4)        // 65536  : Ez, [zi][b]
#define VEC_OFF    (WDUP_BYTES + EZ_BYTES)
#define SMEM_TOTAL (VEC_OFF + 4 * 128 * 4)   // + zsh,tsh,zm,tm  = 198656

__device__ __forceinline__ unsigned long long ffma2(unsigned long long a,
                                                    unsigned long long b,
                                                    unsigned long long c) {
    unsigned long long d;
    asm("fma.rn.f32x2 %0, %1, %2, %3;" : "=l"(d) : "l"(a), "l"(b), "l"(c));
    return d;
}

__device__ __forceinline__ float2 unpack2(unsigned long long v) {
    float2 r;
    asm("mov.b64 {%0, %1}, %2;" : "=f"(r.x), "=f"(r.y) : "l"(v));
    return r;
}

__global__ __launch_bounds__(THREADS, 1)
void gkb_density_kernel(const float* __restrict__ z,
                        const float* __restrict__ t,
                        const float* __restrict__ means,
                        const float* __restrict__ weights,
                        float* __restrict__ out) {
    extern __shared__ char smem_raw[];
    float2* wdup = reinterpret_cast<float2*>(smem_raw);                  // [zi*128 + ti]
    float*  ez   = reinterpret_cast<float*>(smem_raw + WDUP_BYTES);      // [zi*128 + b]
    float*  zsh  = reinterpret_cast<float*>(smem_raw + VEC_OFF);
    float*  tsh  = zsh + 128;
    float*  zm   = tsh + 128;
    float*  tm   = zm + 128;

    const int tid = threadIdx.x;
    const int b0  = blockIdx.x * BB;

    // ---- stage vectors ----
    if (tid < 128) {
        zsh[tid] = z[b0 + tid];
        tsh[tid] = t[b0 + tid];
        // means layout (Z,T,2): zm[zi] = means[(zi*128+0)*2+0], tm[ti] = means[(0*128+ti)*2+1]
        zm[tid] = means[tid * 256];
        tm[tid] = means[tid * 2 + 1];
    }
    __syncthreads();

    // ---- stage Ez (zi-major) and duplicated weights ----
    #pragma unroll 4
    for (int i = tid; i < NZ * BB; i += THREADS) {
        int zi = i >> 7, b = i & 127;
        float d = zsh[b] - zm[zi];
        ez[i] = __expf(-50.0f * d * d);
    }
    #pragma unroll 4
    for (int i = tid; i < NZ * NT; i += THREADS) {
        float w = weights[i] + 0.01f;      // weights is [zi][ti] row-major already
        wdup[i] = make_float2(w, w);
    }
    __syncthreads();

    // ---- register-tiled GEMM with packed f32x2 FMAs ----
    // thread (bx, by): bx = tid%16 owns b in {bx*4..bx*4+3} U {64+bx*4..64+bx*4+3}
    //                  by = tid/16 owns ti in {by*8..by*8+7}
    const int bx = tid & 15;
    const int by = tid >> 4;

    unsigned long long acc[8][2][2];   // [ti_j][b_group][b_pair]
    #pragma unroll
    for (int i = 0; i < 8; i++)
        for (int g = 0; g < 2; g++)
            for (int p = 0; p < 2; p++)
                acc[i][g][p] = 0ull;

    #pragma unroll 4
    for (int zi = 0; zi < NZ; zi++) {
        const float* ezr = ez + (zi << 7);
        ulonglong2 a0 = *reinterpret_cast<const ulonglong2*>(ezr + (bx << 2));
        ulonglong2 a1 = *reinterpret_cast<const ulonglong2*>(ezr + 64 + (bx << 2));
        const ulonglong2* wr =
            reinterpret_cast<const ulonglong2*>(wdup + (zi << 7) + (by << 3));
        ulonglong2 w01 = wr[0];
        ulonglong2 w23 = wr[1];
        ulonglong2 w45 = wr[2];
        ulonglong2 w67 = wr[3];

#define K4(tj, wv)                                    \
        acc[tj][0][0] = ffma2(a0.x, wv, acc[tj][0][0]); \
        acc[tj][0][1] = ffma2(a0.y, wv, acc[tj][0][1]); \
        acc[tj][1][0] = ffma2(a1.x, wv, acc[tj][1][0]); \
        acc[tj][1][1] = ffma2(a1.y, wv, acc[tj][1][1]);

        K4(0, w01.x) K4(1, w01.y) K4(2, w23.x) K4(3, w23.y)
        K4(4, w45.x) K4(5, w45.y) K4(6, w67.x) K4(7, w67.y)
#undef K4
    }

    // ---- epilogue: multiply by Et and partially reduce ----
    float tb[8];
    #pragma unroll
    for (int g = 0; g < 2; g++)
        #pragma unroll
        for (int j = 0; j < 4; j++)
            tb[g * 4 + j] = tsh[g * 64 + (bx << 2) + j];

    float partial[8];
    #pragma unroll
    for (int j = 0; j < 8; j++) partial[j] = 0.0f;

    #pragma unroll
    for (int tj = 0; tj < 8; tj++) {
        float tmv = tm[(by << 3) + tj];
        #pragma unroll
        for (int g = 0; g < 2; g++) {
            #pragma unroll
            for (int p = 0; p < 2; p++) {
                float2 c = unpack2(acc[tj][g][p]);
                float d0 = tb[g * 4 + p * 2]     - tmv;
                float d1 = tb[g * 4 + p * 2 + 1] - tmv;
                float e0 = __expf(-50.0f * d0 * d0);
                float e1 = __expf(-50.0f * d1 * d1);
                partial[g * 4 + p * 2]     += c.x * e0;
                partial[g * 4 + p * 2 + 1] += c.y * e1;
            }
        }
    }

    // ---- cross-thread reduction over the 16 ti-groups (reuse ez region) ----
    __syncthreads();           // everyone done reading ez
    float* red = ez;           // [b_local * 17 + by]
    #pragma unroll
    for (int g = 0; g < 2; g++)
        #pragma unroll
        for (int j = 0; j < 4; j++)
            red[(g * 64 + (bx << 2) + j) * 17 + by] = partial[g * 4 + j];
    __syncthreads();

    if (tid < 128) {
        float s = 0.0f;
        #pragma unroll
        for (int k = 0; k < 16; k++) s += red[tid * 17 + k];
        out[b0 + tid] = -s;
    }
}

extern "C" void kernel_launch(void* const* d_in, const int* in_sizes, int n_in,
                              void* d_out, int out_size) {
    const float* z       = (const float*)d_in[0];
    const float* t       = (const float*)d_in[1];
    const float* means   = (const float*)d_in[2];
    const float* weights = (const float*)d_in[3];
    float* out = (float*)d_out;

    cudaFuncSetAttribute(gkb_density_kernel,
                         cudaFuncAttributeMaxDynamicSharedMemorySize, SMEM_TOTAL);

    const int B = in_sizes[0];           // 16384
    dim3 grid(B / BB), block(THREADS);
    gkb_density_kernel<<<grid, block, SMEM_TOTAL>>>(z, t, means, weights, out);
}

// round 4
// speedup vs baseline: 2.3036x; 2.3036x over previous
#include <cuda_runtime.h>
#include <cuda_fp16.h>
#include <cstdint>

// out[b] = -sum_ti Et[b][ti] * ( sum_zi Ez[b][zi] * (W[zi][ti]+eps) )
// GEMM D[b][ti] = A[b][zi] @ B[zi][ti] via mma.sync.m16n8k16 (f16 in, f32 acc)

#define THREADS 256
#define BB 128
#define LDA 136                       // halves per smem row (272B: conflict-free shift)

#define SMEM_A    0
#define SMEM_B    (128 * LDA * 2)                 // 34816
#define SMEM_VEC  (SMEM_B + 128 * LDA * 2)        // zsh,tsh,zm,tm (4*128*4 = 2048)
#define SMEM_RED  (SMEM_VEC + 2048)               // 128*2 floats
#define SMEM_TOTAL (SMEM_RED + 1024)              // 72704 bytes

__device__ __forceinline__ void mma16816(float* d, const uint32_t* a,
                                         uint32_t b0, uint32_t b1) {
    asm volatile(
        "mma.sync.aligned.m16n8k16.row.col.f32.f16.f16.f32 "
        "{%0,%1,%2,%3}, {%4,%5,%6,%7}, {%8,%9}, {%0,%1,%2,%3};"
        : "+f"(d[0]), "+f"(d[1]), "+f"(d[2]), "+f"(d[3])
        : "r"(a[0]), "r"(a[1]), "r"(a[2]), "r"(a[3]), "r"(b0), "r"(b1));
}

__global__ __launch_bounds__(THREADS, 1)
void gkb_density_kernel(const float* __restrict__ z,
                        const float* __restrict__ t,
                        const float* __restrict__ means,
                        const float* __restrict__ weights,
                        float* __restrict__ out) {
    extern __shared__ char smem[];
    __half* ash = reinterpret_cast<__half*>(smem + SMEM_A);   // Ez [b][zi]
    __half* wsh = reinterpret_cast<__half*>(smem + SMEM_B);   // W' [zi][ti]
    float* zsh = reinterpret_cast<float*>(smem + SMEM_VEC);
    float* tsh = zsh + 128;
    float* zm  = tsh + 128;
    float* tm  = zm + 128;
    float* red = reinterpret_cast<float*>(smem + SMEM_RED);

    const int tid = threadIdx.x;
    const int b0  = blockIdx.x * BB;

    if (tid < 128) {
        zsh[tid] = z[b0 + tid];
        tsh[tid] = t[b0 + tid];
        zm[tid] = means[tid * 256];     // means (Z,T,2): zm[zi]=means[zi][0][0]
        tm[tid] = means[tid * 2 + 1];   //                tm[ti]=means[0][ti][1]
    }
    __syncthreads();

    // ---- stage A = Ez (f16) : 2 elems/thread/iter, coalesced, conflict-free ----
    #pragma unroll
    for (int it = 0; it < 32; it++) {
        int idx = (it * THREADS + tid) * 2;       // b*128 + zi
        int b = idx >> 7, zi = idx & 127;
        float zb = zsh[b];
        float d0 = zb - zm[zi], d1 = zb - zm[zi + 1];
        __half2 h = __floats2half2_rn(__expf(-50.0f * d0 * d0),
                                      __expf(-50.0f * d1 * d1));
        *reinterpret_cast<__half2*>(&ash[b * LDA + zi]) = h;
    }
    // ---- stage B = weights + eps (f16), k-major [zi][ti], coalesced ----
    #pragma unroll
    for (int it = 0; it < 32; it++) {
        int idx = (it * THREADS + tid) * 2;       // zi*128 + ti
        int zi = idx >> 7, ti = idx & 127;
        float2 wv = *reinterpret_cast<const float2*>(&weights[idx]);
        __half2 h = __floats2half2_rn(wv.x + 0.01f, wv.y + 0.01f);
        *reinterpret_cast<__half2*>(&wsh[zi * LDA + ti]) = h;
    }
    __syncthreads();

    // ---- warp-tiled GEMM: 8 warps in 4(m) x 2(n), warp tile 32x64, K=128 ----
    const int lane = tid & 31, wid = tid >> 5;
    const int g = lane >> 2, tg = lane & 3;       // groupID, threadID-in-group
    const int wm = wid >> 1, wn = wid & 1;
    const int m0 = wm * 32, n0 = wn * 64;

    float d[2][8][4];
    #pragma unroll
    for (int mt = 0; mt < 2; mt++)
        #pragma unroll
        for (int nt = 0; nt < 8; nt++)
            #pragma unroll
            for (int e = 0; e < 4; e++) d[mt][nt][e] = 0.0f;

    #pragma unroll
    for (int ks = 0; ks < 8; ks++) {
        const int k0 = ks * 16;
        uint32_t a[2][4];
        #pragma unroll
        for (int mt = 0; mt < 2; mt++) {
            const __half* base = &ash[(m0 + mt * 16 + g) * LDA + k0 + tg * 2];
            a[mt][0] = *reinterpret_cast<const uint32_t*>(base);
            a[mt][1] = *reinterpret_cast<const uint32_t*>(base + 8 * LDA);
            a[mt][2] = *reinterpret_cast<const uint32_t*>(base + 8);
            a[mt][3] = *reinterpret_cast<const uint32_t*>(base + 8 * LDA + 8);
        }
        const int bk = k0 + tg * 2;
        #pragma unroll
        for (int nt = 0; nt < 8; nt++) {
            const __half* bb = &wsh[bk * LDA + n0 + nt * 8 + g];
            uint32_t b0r = (uint32_t)*reinterpret_cast<const uint16_t*>(bb)
                         | ((uint32_t)*reinterpret_cast<const uint16_t*>(bb + LDA) << 16);
            uint32_t b1r = (uint32_t)*reinterpret_cast<const uint16_t*>(bb + 8 * LDA)
                         | ((uint32_t)*reinterpret_cast<const uint16_t*>(bb + 9 * LDA) << 16);
            mma16816(d[0][nt], a[0], b0r, b1r);
            mma16816(d[1][nt], a[1], b0r, b1r);
        }
    }

    // ---- epilogue: fold Et, reduce over ti ----
    // thread owns rows {m0 + mt*16 + h*8 + g}, cols {n0 + nt*8 + tg*2 + e}
    #pragma unroll
    for (int mt = 0; mt < 2; mt++) {
        #pragma unroll
        for (int h = 0; h < 2; h++) {
            const int row = m0 + mt * 16 + h * 8 + g;
            const float tb = tsh[row];
            float acc = 0.0f;
            #pragma unroll
            for (int nt = 0; nt < 8; nt++) {
                const int c0 = n0 + nt * 8 + tg * 2;
                float dt0 = tb - tm[c0];
                float dt1 = tb - tm[c0 + 1];
                acc += d[mt][nt][h * 2 + 0] * __expf(-50.0f * dt0 * dt0);
                acc += d[mt][nt][h * 2 + 1] * __expf(-50.0f * dt1 * dt1);
            }
            // reduce over the 4 lanes of the quad (tg axis covers all cols)
            acc += __shfl_xor_sync(0xffffffffu, acc, 1);
            acc += __shfl_xor_sync(0xffffffffu, acc, 2);
            if (tg == 0) red[row * 2 + wn] = acc;
        }
    }
    __syncthreads();
    if (tid < 128) out[b0 + tid] = -(red[tid * 2] + red[tid * 2 + 1]);
}

extern "C" void kernel_launch(void* const* d_in, const int* in_sizes, int n_in,
                              void* d_out, int out_size) {
    const float* z       = (const float*)d_in[0];
    const float* t       = (const float*)d_in[1];
    const float* means   = (const float*)d_in[2];
    const float* weights = (const float*)d_in[3];
    float* out = (float*)d_out;

    cudaFuncSetAttribute(gkb_density_kernel,
                         cudaFuncAttributeMaxDynamicSharedMemorySize, SMEM_TOTAL);

    const int B = in_sizes[0];           // 16384
    dim3 grid(B / BB), block(THREADS);
    gkb_density_kernel<<<grid, block, SMEM_TOTAL>>>(z, t, means, weights, out);
}

// round 6
// speedup vs baseline: 2.8145x; 1.2218x over previous
#include <cuda_runtime.h>
#include <cuda_fp16.h>
#include <cstdint>

// out[b] = -sum_ti Et[b][ti] * ( sum_zi Ez[b][zi] * (W[zi][ti]+eps) )
// GEMM D[b][ti] = A[b][zi] @ B[zi][ti], mma.m16n8k16 + ldmatrix, BB=64 rows/CTA.

#define THREADS 256
#define BB 64
#define LDA 136                       // halves per smem row (272B): LDSM conflict-free

#define SMEM_A    0                                  // Ez:  64 x LDA f16 = 17408
#define SMEM_B    (BB * LDA * 2)                     // W': 128 x LDA f16 = 34816
#define SMEM_VEC  (SMEM_B + 128 * LDA * 2)           // zsh(64),tsh(64),zm(128),tm(128)
#define SMEM_RED  (SMEM_VEC + (64 + 64 + 128 + 128) * 4)
#define SMEM_TOTAL (SMEM_RED + BB * 4 * 4)           // red: 64 rows x 4 wn

__device__ __forceinline__ void mma16816(float* d, const uint32_t* a,
                                         uint32_t b0, uint32_t b1) {
    asm volatile(
        "mma.sync.aligned.m16n8k16.row.col.f32.f16.f16.f32 "
        "{%0,%1,%2,%3}, {%4,%5,%6,%7}, {%8,%9}, {%0,%1,%2,%3};"
        : "+f"(d[0]), "+f"(d[1]), "+f"(d[2]), "+f"(d[3])
        : "r"(a[0]), "r"(a[1]), "r"(a[2]), "r"(a[3]), "r"(b0), "r"(b1));
}
__device__ __forceinline__ uint32_t smem_u32(const void* p) {
    uint32_t a;
    asm("{ .reg .u64 t; cvta.to.shared.u64 t, %1; cvt.u32.u64 %0, t; }" : "=r"(a) : "l"(p));
    return a;
}
__device__ __forceinline__ void ldsm_x4(uint32_t* r, uint32_t addr) {
    asm volatile("ldmatrix.sync.aligned.m8n8.x4.shared.b16 {%0,%1,%2,%3}, [%4];"
                 : "=r"(r[0]), "=r"(r[1]), "=r"(r[2]), "=r"(r[3]) : "r"(addr));
}
__device__ __forceinline__ void ldsm_x4_trans(uint32_t* r, uint32_t addr) {
    asm volatile("ldmatrix.sync.aligned.m8n8.x4.trans.shared.b16 {%0,%1,%2,%3}, [%4];"
                 : "=r"(r[0]), "=r"(r[1]), "=r"(r[2]), "=r"(r[3]) : "r"(addr));
}

__global__ __launch_bounds__(THREADS, 2)
void gkb_density_kernel(const float* __restrict__ z,
                        const float* __restrict__ t,
                        const float* __restrict__ means,
                        const float* __restrict__ weights,
                        float* __restrict__ out) {
    extern __shared__ char smem[];
    __half* ash = reinterpret_cast<__half*>(smem + SMEM_A);   // Ez [b][zi], 64 rows
    __half* wsh = reinterpret_cast<__half*>(smem + SMEM_B);   // W' [zi][ti], 128 rows
    float* zsh = reinterpret_cast<float*>(smem + SMEM_VEC);   // 64
    float* tsh = zsh + 64;                                    // 64
    float* zm  = tsh + 64;                                    // 128
    float* tm  = zm + 128;                                    // 128
    float* red = reinterpret_cast<float*>(smem + SMEM_RED);   // [64][4]

    const int tid = threadIdx.x;
    const int b0  = blockIdx.x * BB;

    if (tid < 64) {
        zsh[tid] = z[b0 + tid];
        tsh[tid] = t[b0 + tid];
    }
    if (tid < 128) {
        zm[tid] = means[tid * 256];     // means (Z,T,2): zm[zi]=means[zi][0][0]
        tm[tid] = means[tid * 2 + 1];   //                tm[ti]=means[0][ti][1]
    }
    __syncthreads();

    // ---- stage A = Ez (f16): 64x128, 2 elems/thread/iter ----
    #pragma unroll
    for (int it = 0; it < 16; it++) {
        int idx = (it * THREADS + tid) * 2;       // b*128 + zi
        int b = idx >> 7, zi = idx & 127;
        float zb = zsh[b];
        float d0 = zb - zm[zi], d1 = zb - zm[zi + 1];
        __half2 h = __floats2half2_rn(__expf(-50.0f * d0 * d0),
                                      __expf(-50.0f * d1 * d1));
        *reinterpret_cast<__half2*>(&ash[b * LDA + zi]) = h;
    }
    // ---- stage B = weights + eps (f16), k-major [zi][ti] ----
    #pragma unroll
    for (int it = 0; it < 32; it++) {
        int idx = (it * THREADS + tid) * 2;       // zi*128 + ti
        int zi = idx >> 7, ti = idx & 127;
        float2 wv = *reinterpret_cast<const float2*>(&weights[idx]);
        __half2 h = __floats2half2_rn(wv.x + 0.01f, wv.y + 0.01f);
        *reinterpret_cast<__half2*>(&wsh[zi * LDA + ti]) = h;
    }
    __syncthreads();

    // ---- warp-tiled GEMM: 8 warps in 2(m) x 4(n), warp tile 32x32, K=128 ----
    const int lane = tid & 31, wid = tid >> 5;
    const int g = lane >> 2, tg = lane & 3;
    const int wm = wid >> 2, wn = wid & 3;
    const int m0 = wm * 32, n0 = wn * 32;

    // LDSM lane addressing
    const int lr = lane & 15, lc = lane >> 4;     // row-in-16, col-group
    const uint32_t a_lane0 = smem_u32(&ash[(m0 + lr) * LDA + lc * 8]);
    const uint32_t b_lane0 = smem_u32(&wsh[lr * LDA + n0 + lc * 8]);

    float d[2][4][4];
    #pragma unroll
    for (int mt = 0; mt < 2; mt++)
        #pragma unroll
        for (int nt = 0; nt < 4; nt++)
            #pragma unroll
            for (int e = 0; e < 4; e++) d[mt][nt][e] = 0.0f;

    #pragma unroll
    for (int ks = 0; ks < 8; ks++) {
        uint32_t a[2][4], b[2][4];
        ldsm_x4(a[0], a_lane0 + ks * 32);                    // m0..m0+15, k16
        ldsm_x4(a[1], a_lane0 + 16 * LDA * 2 + ks * 32);     // m0+16..31
        ldsm_x4_trans(b[0], b_lane0 + ks * 16 * LDA * 2);    // n0..n0+15, k16
        ldsm_x4_trans(b[1], b_lane0 + ks * 16 * LDA * 2 + 32); // n0+16..n0+31
        #pragma unroll
        for (int mt = 0; mt < 2; mt++)
            #pragma unroll
            for (int nb = 0; nb < 2; nb++) {
                mma16816(d[mt][nb * 2],     a[mt], b[nb][0], b[nb][1]);
                mma16816(d[mt][nb * 2 + 1], a[mt], b[nb][2], b[nb][3]);
            }
    }

    // ---- epilogue: fold Et, reduce over ti ----
    // thread covers rows {m0 + mt*16 + h*8 + g}, cols {n0 + nt*8 + tg*2 + e}
    #pragma unroll
    for (int mt = 0; mt < 2; mt++) {
        #pragma unroll
        for (int h = 0; h < 2; h++) {
            const int row = m0 + mt * 16 + h * 8 + g;
            const float tb = tsh[row];
            float acc = 0.0f;
            #pragma unroll
            for (int nt = 0; nt < 4; nt++) {
                const int c0 = n0 + nt * 8 + tg * 2;
                float dt0 = tb - tm[c0];
                float dt1 = tb - tm[c0 + 1];
                acc += d[mt][nt][h * 2 + 0] * __expf(-50.0f * dt0 * dt0);
                acc += d[mt][nt][h * 2 + 1] * __expf(-50.0f * dt1 * dt1);
            }
            acc += __shfl_xor_sync(0xffffffffu, acc, 1);
            acc += __shfl_xor_sync(0xffffffffu, acc, 2);
            if (tg == 0) red[row * 4 + wn] = acc;
        }
    }
    __syncthreads();
    if (tid < BB) {
        const float* r = &red[tid * 4];
        out[b0 + tid] = -(r[0] + r[1] + r[2] + r[3]);
    }
}

extern "C" void kernel_launch(void* const* d_in, const int* in_sizes, int n_in,
                              void* d_out, int out_size) {
    const float* z       = (const float*)d_in[0];
    const float* t       = (const float*)d_in[1];
    const float* means   = (const float*)d_in[2];
    const float* weights = (const float*)d_in[3];
    float* out = (float*)d_out;

    cudaFuncSetAttribute(gkb_density_kernel,
                         cudaFuncAttributeMaxDynamicSharedMemorySize, SMEM_TOTAL);

    const int B = in_sizes[0];           // 16384
    dim3 grid(B / BB), block(THREADS);
    gkb_density_kernel<<<grid, block, SMEM_TOTAL>>>(z, t, means, weights, out);
}